// round 16
// baseline (speedup 1.0000x reference)
#include <cuda_runtime.h>
#include <cuda_bf16.h>
#include <cstdint>
#include <math.h>

#define BATCH 8192
#define NC    2048
#define NF    512          // features; also bytes per int8 row

#define BM 128
#define BN 128
#define BKB 128            // K-tile bytes (128 int8 = 128B/row = SW128-ish swizzle unit)
#define NT (NF / BKB)      // 4 K-tiles
#define NSTAGE 3

// ---------------- device scratch (no allocs allowed) ----------------
__device__ float g_xsq[BATCH];
__device__ float g_csq[NC];
__device__ float g_inv2s[NC];
__device__ float g_rsx[BATCH];   // dequant scale per A row (rowmax/127)
__device__ float g_rsc[NC];      // dequant scale per B row
__device__ int8_t g_Aq[(size_t)BATCH * NF];
__device__ int8_t g_Bq[(size_t)NC * NF];

// ---------------- portable PTX helpers (sm_80+ features only) ----------------
__device__ __forceinline__ uint32_t smem_u32(const void* p) {
    uint32_t a;
    asm("{ .reg .u64 t; cvta.to.shared.u64 t, %1; cvt.u32.u64 %0, t; }"
        : "=r"(a) : "l"(p));
    return a;
}

__device__ __forceinline__ void cp_async16(uint32_t dst, const void* src) {
    asm volatile("cp.async.cg.shared.global [%0], [%1], 16;"
                 :: "r"(dst), "l"(src) : "memory");
}
#define CP_COMMIT() asm volatile("cp.async.commit_group;" ::: "memory")
#define CP_WAIT_1() asm volatile("cp.async.wait_group 1;" ::: "memory")
#define CP_WAIT_0() asm volatile("cp.async.wait_group 0;" ::: "memory")

__device__ __forceinline__ void ldsm_x4(uint32_t* r, uint32_t addr) {
    asm volatile("ldmatrix.sync.aligned.m8n8.x4.shared.b16 {%0,%1,%2,%3}, [%4];"
                 : "=r"(r[0]), "=r"(r[1]), "=r"(r[2]), "=r"(r[3]) : "r"(addr));
}

// int8 IMMA: m16n8k32, s32 accumulate. A frag 4 regs, B frag 2 regs.
__device__ __forceinline__ void mma_s8(int* c, const uint32_t* a,
                                       uint32_t b0, uint32_t b1) {
    asm volatile("mma.sync.aligned.m16n8k32.row.col.s32.s8.s8.s32 "
                 "{%0,%1,%2,%3}, {%4,%5,%6,%7}, {%8,%9}, {%0,%1,%2,%3};"
                 : "+r"(c[0]), "+r"(c[1]), "+r"(c[2]), "+r"(c[3])
                 : "r"(a[0]), "r"(a[1]), "r"(a[2]), "r"(a[3]), "r"(b0), "r"(b1));
}

// ---------------- SMEM layout (dynamic) ----------------
static constexpr int A_BYTES = BM * BKB;                 // 16384
static constexpr int B_BYTES = BN * BKB;                 // 16384
static constexpr int STAGE_BYTES = A_BYTES + B_BYTES;    // 32768
static constexpr int OFF_STAGE0 = 0;
static constexpr int OFF_XS = OFF_STAGE0 + NSTAGE * STAGE_BYTES;  // 98304
static constexpr int OFF_CS = OFF_XS + 512;
static constexpr int OFF_IS = OFF_CS + 512;
static constexpr int OFF_RX = OFF_IS + 512;   // rsx per M row
static constexpr int OFF_MC = OFF_RX + 512;   // -2*rsc per N col
static constexpr int SMEM_TOTAL = OFF_MC + 512;          // 100864 bytes

// ---------------- prologue: fp32 -> int8 rows + norms + scales + sigma ----------------
__global__ void prologue_kernel(const float* __restrict__ A,
                                const float* __restrict__ B,
                                const float* __restrict__ sig,
                                int8_t* __restrict__ Aq,
                                int8_t* __restrict__ Bq,
                                float* __restrict__ xsq,
                                float* __restrict__ csq,
                                float* __restrict__ rsx,
                                float* __restrict__ rsc,
                                float* __restrict__ inv2s) {
    const int ablocks = BATCH / 8;
    int lane = threadIdx.x & 31;
    int wrow = blockIdx.x * 8 + (threadIdx.x >> 5);

    const float* X; int8_t* Xq; float* nrm; float* rsp; int row;
    if (blockIdx.x < ablocks) { X = A; Xq = Aq; nrm = xsq; rsp = rsx; row = wrow; }
    else { X = B; Xq = Bq; nrm = csq; rsp = rsc; row = wrow - BATCH; }

    const float4* p = reinterpret_cast<const float4*>(X + (size_t)row * NF);
    float4 v[4];
    float s = 0.f, mx = 0.f;
    #pragma unroll
    for (int i = 0; i < 4; i++) {
        v[i] = p[lane + i * 32];
        s += v[i].x * v[i].x + v[i].y * v[i].y + v[i].z * v[i].z + v[i].w * v[i].w;
        mx = fmaxf(mx, fmaxf(fmaxf(fabsf(v[i].x), fabsf(v[i].y)),
                             fmaxf(fabsf(v[i].z), fabsf(v[i].w))));
    }
    #pragma unroll
    for (int o = 16; o; o >>= 1) {
        s  += __shfl_xor_sync(0xffffffffu, s, o);
        mx  = fmaxf(mx, __shfl_xor_sync(0xffffffffu, mx, o));
    }
    const float scale = 127.0f / mx;
    if (lane == 0) { nrm[row] = s; rsp[row] = mx * (1.0f / 127.0f); }

    uint32_t* q = reinterpret_cast<uint32_t*>(Xq + (size_t)row * NF);
    #pragma unroll
    for (int i = 0; i < 4; i++) {
        int x0 = __float2int_rn(v[i].x * scale);
        int x1 = __float2int_rn(v[i].y * scale);
        int x2 = __float2int_rn(v[i].z * scale);
        int x3 = __float2int_rn(v[i].w * scale);
        uint32_t pk = (uint32_t)(x0 & 0xFF) | ((uint32_t)(x1 & 0xFF) << 8) |
                      ((uint32_t)(x2 & 0xFF) << 16) | ((uint32_t)(x3 & 0xFF) << 24);
        q[lane + i * 32] = pk;
    }

    int si = blockIdx.x * blockDim.x + threadIdx.x;
    if (si < NC) {
        float sg = sig[si];
        inv2s[si] = 1.0f / (2.0f * sg * sg);
    }
}

// ---------------- IMMA GEMM 128x128, 4 warps of 64x64, fused RBF ----------------
__global__ __launch_bounds__(128, 2)
void rbf_imma_kernel(const int8_t* __restrict__ Aq,
                     const int8_t* __restrict__ Bq,
                     const float* __restrict__ xsq,
                     const float* __restrict__ csq,
                     const float* __restrict__ inv2s,
                     const float* __restrict__ rsx,
                     const float* __restrict__ rsc,
                     float* __restrict__ C) {
    extern __shared__ char smem[];
    const uint32_t sb = smem_u32(smem);
    const int tid = threadIdx.x;
    const int wid = tid >> 5;
    const int lid = tid & 31;
    const int bx = blockIdx.x;           // N tile
    const int by = blockIdx.y;           // M tile
    const int warp_m = wid & 1;          // 2 m-warps * 64 rows
    const int warp_n = wid >> 1;         // 2 n-warps * 64 cols

    // stage per-tile scalars (128 entries each; all 128 threads)
    reinterpret_cast<float*>(smem + OFF_XS)[tid] = xsq[by * BM + tid];
    reinterpret_cast<float*>(smem + OFF_CS)[tid] = csq[bx * BN + tid];
    reinterpret_cast<float*>(smem + OFF_IS)[tid] = inv2s[bx * BN + tid];
    reinterpret_cast<float*>(smem + OFF_RX)[tid] = rsx[by * BM + tid];
    reinterpret_cast<float*>(smem + OFF_MC)[tid] = -2.0f * rsc[bx * BN + tid];

    // ---- cp.async addressing ----
    const int ld_row0 = tid >> 3;        // 0..15
    const int ld_c16  = tid & 7;         // 16B chunk within 128B k-tile row
    const int8_t* agp = Aq + (size_t)(by * BM + ld_row0) * NF + ld_c16 * 16;
    const int8_t* bgp = Bq + (size_t)(bx * BN + ld_row0) * NF + ld_c16 * 16;
    const uint32_t sdst0 = (uint32_t)ld_row0 * 128 +
                           ((uint32_t)(ld_c16 ^ (ld_row0 & 7)) << 4);

    auto load_tile = [&](int kt, int stage) {
        const uint32_t base = sb + OFF_STAGE0 + stage * STAGE_BYTES;
        const int k0 = kt * BKB;         // byte offset along row
        #pragma unroll
        for (int i = 0; i < 8; i++) {    // rows ld_row0 + 16*i
            cp_async16(base + sdst0 + i * 2048, agp + k0 + (size_t)i * 16 * NF);
            cp_async16(base + A_BYTES + sdst0 + i * 2048, bgp + k0 + (size_t)i * 16 * NF);
        }
    };

    // ---- ldmatrix lane geometry (identical tiles to bf16 version) ----
    const int lrow = lid & 15;
    const int lchk = lid >> 4;
    const int rowA0 = warp_m * 64 + lrow;
    const int rowB0 = warp_n * 64 + lrow;
    const uint32_t xA = (uint32_t)(rowA0 & 7);
    const uint32_t xB = (uint32_t)(rowB0 & 7);
    const uint32_t rA_off0 = (uint32_t)rowA0 * 128;
    const uint32_t rB_off0 = (uint32_t)rowB0 * 128;

    // per-k32-step swizzled chunk offsets (t-invariant): step s covers chunks 2s,2s+1
    uint32_t swA[4], swB[4];
    #pragma unroll
    for (int s = 0; s < 4; s++) {
        const uint32_t cc = (uint32_t)(s * 2 + lchk);
        swA[s] = ((cc ^ xA) & 7) << 4;
        swB[s] = ((cc ^ xB) & 7) << 4;
    }

    int acc[4][8][4];
    #pragma unroll
    for (int mi = 0; mi < 4; mi++)
        #pragma unroll
        for (int n = 0; n < 8; n++)
            #pragma unroll
            for (int v = 0; v < 4; v++) acc[mi][n][v] = 0;

    load_tile(0, 0); CP_COMMIT();
    load_tile(1, 1); CP_COMMIT();

    for (int t = 0; t < NT; t++) {
        if (t == NT - 1) { CP_WAIT_0(); } else { CP_WAIT_1(); }
        __syncthreads();
        if (t + 2 < NT) { load_tile(t + 2, (t + 2) % NSTAGE); CP_COMMIT(); }

        const uint32_t baseA = sb + OFF_STAGE0 + (t % NSTAGE) * STAGE_BYTES;
        const uint32_t baseB = baseA + A_BYTES;

        #pragma unroll
        for (int s = 0; s < 4; s++) {    // 4 k32-steps per 128B tile
            uint32_t a[4][4], b[4][4];
            #pragma unroll
            for (int mi = 0; mi < 4; mi++)
                ldsm_x4(a[mi], baseA + rA_off0 + mi * 2048 + swA[s]);
            #pragma unroll
            for (int nq = 0; nq < 4; nq++)
                ldsm_x4(b[nq], baseB + rB_off0 + nq * 2048 + swB[s]);
            #pragma unroll
            for (int mi = 0; mi < 4; mi++)
                #pragma unroll
                for (int nq = 0; nq < 4; nq++) {
                    // x4 B covers n16: {r0,r2} = cols 0-7, {r1,r3} = cols 8-15
                    mma_s8(acc[mi][nq * 2 + 0], a[mi], b[nq][0], b[nq][2]);
                    mma_s8(acc[mi][nq * 2 + 1], a[mi], b[nq][1], b[nq][3]);
                }
        }
    }

    // ---------------- fused RBF epilogue (dequant + exp) ----------------
    const float* xs = reinterpret_cast<const float*>(smem + OFF_XS);
    const float* cs = reinterpret_cast<const float*>(smem + OFF_CS) + warp_n * 64;
    const float* is = reinterpret_cast<const float*>(smem + OFF_IS) + warp_n * 64;
    const float* rx = reinterpret_cast<const float*>(smem + OFF_RX);
    const float* mc = reinterpret_cast<const float*>(smem + OFF_MC) + warp_n * 64;
    const int l4 = lid >> 2;
    const int l2 = (lid & 3) * 2;

    #pragma unroll
    for (int mi = 0; mi < 4; mi++) {
        #pragma unroll
        for (int h = 0; h < 2; h++) {
            const int r = warp_m * 64 + mi * 16 + h * 8 + l4;
            const float xm = xs[r];
            const float ar = rx[r];      // row dequant scale
            float* crow = C + (size_t)(by * BM + r) * NC + bx * BN + warp_n * 64;
            #pragma unroll
            for (int n = 0; n < 8; n++) {
                const int cidx = n * 8 + l2;
                // d = xm + cs - 2 * (acc * ar * rsc) ;  mc = -2*rsc
                float f0 = (float)acc[mi][n][h * 2 + 0];
                float f1 = (float)acc[mi][n][h * 2 + 1];
                float d0 = fmaf(f0, ar * mc[cidx],     xm + cs[cidx]);
                float d1 = fmaf(f1, ar * mc[cidx + 1], xm + cs[cidx + 1]);
                float2 o;
                o.x = __expf(-fmaxf(d0, 0.0f) * is[cidx]);
                o.y = __expf(-fmaxf(d1, 0.0f) * is[cidx + 1]);
                *reinterpret_cast<float2*>(crow + cidx) = o;
            }
        }
    }
}

// ---------------- launch ----------------
extern "C" void kernel_launch(void* const* d_in, const int* in_sizes, int n_in,
                              void* d_out, int out_size) {
    const float* inputs  = (const float*)d_in[0];
    const float* centers = (const float*)d_in[1];
    const float* sigmas  = (const float*)d_in[2];
    float* out = (float*)d_out;

    float *xsq, *csq, *inv2s, *rsx, *rsc;
    int8_t *Aq, *Bq;
    cudaGetSymbolAddress((void**)&xsq,   g_xsq);
    cudaGetSymbolAddress((void**)&csq,   g_csq);
    cudaGetSymbolAddress((void**)&inv2s, g_inv2s);
    cudaGetSymbolAddress((void**)&rsx,   g_rsx);
    cudaGetSymbolAddress((void**)&rsc,   g_rsc);
    cudaGetSymbolAddress((void**)&Aq,    g_Aq);
    cudaGetSymbolAddress((void**)&Bq,    g_Bq);

    cudaFuncSetAttribute(rbf_imma_kernel,
                         cudaFuncAttributeMaxDynamicSharedMemorySize, SMEM_TOTAL);

    prologue_kernel<<<(BATCH + NC) / 8, 256>>>(inputs, centers, sigmas,
                                               Aq, Bq, xsq, csq, rsx, rsc, inv2s);

    dim3 grid(NC / BN, BATCH / BM);   // (16, 64)
    rbf_imma_kernel<<<grid, 128, SMEM_TOTAL>>>(Aq, Bq, xsq, csq, inv2s, rsx, rsc, out);
}

// round 17
// speedup vs baseline: 2.3035x; 2.3035x over previous
#include <cuda_runtime.h>
#include <cuda_fp16.h>
#include <cstdint>
#include <math.h>

#define BATCH 8192
#define NC    2048
#define NF    512

#define BM 128
#define BN 128
#define BK 64          // fp16 elems per K-tile (128 bytes/row)
#define NT (NF / BK)   // 8 K-tiles
#define NSTAGE 3

// ---------------- device scratch (no allocs allowed) ----------------
__device__ float g_xsq[BATCH];
__device__ float g_csq[NC];
__device__ float g_inv2s[NC];
__device__ __half g_Ah[(size_t)BATCH * NF];
__device__ __half g_Bh[(size_t)NC * NF];

// ---------------- portable PTX helpers (sm_80+ features only) ----------------
__device__ __forceinline__ uint32_t smem_u32(const void* p) {
    uint32_t a;
    asm("{ .reg .u64 t; cvta.to.shared.u64 t, %1; cvt.u32.u64 %0, t; }"
        : "=r"(a) : "l"(p));
    return a;
}

__device__ __forceinline__ void cp_async16(uint32_t dst, const void* src) {
    asm volatile("cp.async.cg.shared.global [%0], [%1], 16;"
                 :: "r"(dst), "l"(src) : "memory");
}
#define CP_COMMIT() asm volatile("cp.async.commit_group;" ::: "memory")
#define CP_WAIT_1() asm volatile("cp.async.wait_group 1;" ::: "memory")
#define CP_WAIT_0() asm volatile("cp.async.wait_group 0;" ::: "memory")

__device__ __forceinline__ void ldsm_x4(uint32_t* r, uint32_t addr) {
    asm volatile("ldmatrix.sync.aligned.m8n8.x4.shared.b16 {%0,%1,%2,%3}, [%4];"
                 : "=r"(r[0]), "=r"(r[1]), "=r"(r[2]), "=r"(r[3]) : "r"(addr));
}

// fp16 mma with fp16 accumulation: C/D frag = 2 regs (4 halves)
__device__ __forceinline__ void mma_f16acc(uint32_t* c, const uint32_t* a,
                                           uint32_t b0, uint32_t b1) {
    asm volatile("mma.sync.aligned.m16n8k16.row.col.f16.f16.f16.f16 "
                 "{%0,%1}, {%2,%3,%4,%5}, {%6,%7}, {%0,%1};"
                 : "+r"(c[0]), "+r"(c[1])
                 : "r"(a[0]), "r"(a[1]), "r"(a[2]), "r"(a[3]), "r"(b0), "r"(b1));
}

// ---------------- SMEM layout (dynamic) ----------------
static constexpr int A_BYTES = BM * 128;                 // 16384
static constexpr int B_BYTES = BN * 128;                 // 16384
static constexpr int STAGE_BYTES = A_BYTES + B_BYTES;    // 32768
static constexpr int OFF_STAGE0 = 0;
static constexpr int OFF_XS = OFF_STAGE0 + NSTAGE * STAGE_BYTES;  // 98304
static constexpr int OFF_CS = OFF_XS + 512;
static constexpr int OFF_IS = OFF_CS + 512;
static constexpr int SMEM_TOTAL = OFF_IS + 512;          // 99840 bytes

// ---------------- merged prologue: fp32 -> fp16 + norms + sigma ----------------
__global__ void prologue_kernel(const float* __restrict__ A,
                                const float* __restrict__ B,
                                const float* __restrict__ sig,
                                __half* __restrict__ Ah,
                                __half* __restrict__ Bh,
                                float* __restrict__ xsq,
                                float* __restrict__ csq,
                                float* __restrict__ inv2s) {
    const int ablocks = BATCH / 8;
    int lane = threadIdx.x & 31;
    int wrow = blockIdx.x * 8 + (threadIdx.x >> 5);

    const float* X; __half* Xh; float* nrm; int row;
    if (blockIdx.x < ablocks) { X = A; Xh = Ah; nrm = xsq; row = wrow; }
    else { X = B; Xh = Bh; nrm = csq; row = wrow - BATCH; }

    const float4* p = reinterpret_cast<const float4*>(X + (size_t)row * NF);
    __half2* q = reinterpret_cast<__half2*>(Xh + (size_t)row * NF);
    float s = 0.f;
    #pragma unroll
    for (int i = 0; i < NF / 4 / 32; i++) {
        int idx = lane + i * 32;
        float4 v = p[idx];
        s += v.x * v.x + v.y * v.y + v.z * v.z + v.w * v.w;
        q[idx * 2]     = __floats2half2_rn(v.x, v.y);
        q[idx * 2 + 1] = __floats2half2_rn(v.z, v.w);
    }
    #pragma unroll
    for (int o = 16; o; o >>= 1) s += __shfl_xor_sync(0xffffffffu, s, o);
    if (lane == 0) nrm[row] = s;

    int si = blockIdx.x * blockDim.x + threadIdx.x;
    if (si < NC) {
        float sg = sig[si];
        inv2s[si] = 1.0f / (2.0f * sg * sg);
    }
}

// ---------------- HMMA-f16acc GEMM 128x128, 4 warps of 64x64, fused RBF ----------------
__global__ __launch_bounds__(128, 2)
void rbf_mma_kernel(const __half* __restrict__ Ah,
                    const __half* __restrict__ Bh,
                    const float* __restrict__ xsq,
                    const float* __restrict__ csq,
                    const float* __restrict__ inv2s,
                    float* __restrict__ C) {
    extern __shared__ char smem[];
    const uint32_t sb = smem_u32(smem);
    const int tid = threadIdx.x;
    const int wid = tid >> 5;
    const int lid = tid & 31;
    const int bx = blockIdx.x;           // N tile
    const int by = blockIdx.y;           // M tile
    const int warp_m = wid & 1;          // 2 m-warps * 64 rows
    const int warp_n = wid >> 1;         // 2 n-warps * 64 cols

    // stage per-tile xsq / csq / inv2s
    reinterpret_cast<float*>(smem + OFF_XS)[tid] = xsq[by * BM + tid];
    reinterpret_cast<float*>(smem + OFF_CS)[tid] = csq[bx * BN + tid];
    reinterpret_cast<float*>(smem + OFF_IS)[tid] = inv2s[bx * BN + tid];

    // ---- cp.async addressing ----
    const int ld_row0 = tid >> 3;        // 0..15
    const int ld_c16  = tid & 7;
    const __half* agp = Ah + (size_t)(by * BM + ld_row0) * NF + ld_c16 * 8;
    const __half* bgp = Bh + (size_t)(bx * BN + ld_row0) * NF + ld_c16 * 8;
    const uint32_t sdst0 = (uint32_t)ld_row0 * 128 +
                           ((uint32_t)(ld_c16 ^ (ld_row0 & 7)) << 4);

    auto load_tile = [&](int kt, int stage) {
        const uint32_t base = sb + OFF_STAGE0 + stage * STAGE_BYTES;
        const int k0 = kt * BK;
        #pragma unroll
        for (int i = 0; i < 8; i++) {    // rows ld_row0 + 16*i
            cp_async16(base + sdst0 + i * 2048, agp + k0 + (size_t)i * 16 * NF);
            cp_async16(base + A_BYTES + sdst0 + i * 2048, bgp + k0 + (size_t)i * 16 * NF);
        }
    };

    // ---- ldmatrix lane geometry ----
    const int lrow = lid & 15;
    const int lchk = lid >> 4;
    const int rowA0 = warp_m * 64 + lrow;
    const int rowB0 = warp_n * 64 + lrow;
    const uint32_t xA = (uint32_t)(rowA0 & 7);
    const uint32_t xB = (uint32_t)(rowB0 & 7);
    const uint32_t rA_off0 = (uint32_t)rowA0 * 128;
    const uint32_t rB_off0 = (uint32_t)rowB0 * 128;

    uint32_t swA[4], swB[4];
    #pragma unroll
    for (int s = 0; s < 4; s++) {
        const uint32_t cc = (uint32_t)(s * 2 + lchk);
        swA[s] = ((cc ^ xA) & 7) << 4;
        swB[s] = ((cc ^ xB) & 7) << 4;
    }

    // fp16 accumulators: [mi][n8][2 regs]; reg h covers rows h*8..h*8+7
    uint32_t acc[4][8][2];
    #pragma unroll
    for (int mi = 0; mi < 4; mi++)
        #pragma unroll
        for (int n = 0; n < 8; n++)
            { acc[mi][n][0] = 0u; acc[mi][n][1] = 0u; }

    load_tile(0, 0); CP_COMMIT();
    load_tile(1, 1); CP_COMMIT();

    for (int t = 0; t < NT; t++) {
        if (t == NT - 1) { CP_WAIT_0(); } else { CP_WAIT_1(); }
        __syncthreads();
        if (t + 2 < NT) { load_tile(t + 2, (t + 2) % NSTAGE); CP_COMMIT(); }

        const uint32_t baseA = sb + OFF_STAGE0 + (t % NSTAGE) * STAGE_BYTES;
        const uint32_t baseB = baseA + A_BYTES;

        #pragma unroll
        for (int s = 0; s < BK / 16; s++) {
            uint32_t a[4][4], b[4][4];
            #pragma unroll
            for (int mi = 0; mi < 4; mi++)
                ldsm_x4(a[mi], baseA + rA_off0 + mi * 2048 + swA[s]);
            #pragma unroll
            for (int nq = 0; nq < 4; nq++)
                ldsm_x4(b[nq], baseB + rB_off0 + nq * 2048 + swB[s]);
            #pragma unroll
            for (int mi = 0; mi < 4; mi++)
                #pragma unroll
                for (int nq = 0; nq < 4; nq++) {
                    mma_f16acc(acc[mi][nq * 2 + 0], a[mi], b[nq][0], b[nq][2]);
                    mma_f16acc(acc[mi][nq * 2 + 1], a[mi], b[nq][1], b[nq][3]);
                }
        }
    }

    // ---------------- fused RBF epilogue (half2 -> float) ----------------
    const float* xs = reinterpret_cast<const float*>(smem + OFF_XS);
    const float* cs = reinterpret_cast<const float*>(smem + OFF_CS) + warp_n * 64;
    const float* is = reinterpret_cast<const float*>(smem + OFF_IS) + warp_n * 64;
    const int l4 = lid >> 2;
    const int l2 = (lid & 3) * 2;

    #pragma unroll
    for (int mi = 0; mi < 4; mi++) {
        #pragma unroll
        for (int h = 0; h < 2; h++) {    // acc reg h = rows h*8..h*8+7 of the 16-row tile
            const int r = warp_m * 64 + mi * 16 + h * 8 + l4;
            const float xm = xs[r];
            float* crow = C + (size_t)(by * BM + r) * NC + bx * BN + warp_n * 64;
            #pragma unroll
            for (int n = 0; n < 8; n++) {
                const int cidx = n * 8 + l2;
                float2 f = __half22float2(
                    *reinterpret_cast<const __half2*>(&acc[mi][n][h]));
                float d0 = fmaf(-2.0f, f.x, xm + cs[cidx]);
                float d1 = fmaf(-2.0f, f.y, xm + cs[cidx + 1]);
                float2 o;
                o.x = __expf(-fmaxf(d0, 0.0f) * is[cidx]);
                o.y = __expf(-fmaxf(d1, 0.0f) * is[cidx + 1]);
                *reinterpret_cast<float2*>(crow + cidx) = o;
            }
        }
    }
}

// ---------------- launch ----------------
extern "C" void kernel_launch(void* const* d_in, const int* in_sizes, int n_in,
                              void* d_out, int out_size) {
    const float* inputs  = (const float*)d_in[0];
    const float* centers = (const float*)d_in[1];
    const float* sigmas  = (const float*)d_in[2];
    float* out = (float*)d_out;

    float *xsq, *csq, *inv2s;
    __half *Ah, *Bh;
    cudaGetSymbolAddress((void**)&xsq,   g_xsq);
    cudaGetSymbolAddress((void**)&csq,   g_csq);
    cudaGetSymbolAddress((void**)&inv2s, g_inv2s);
    cudaGetSymbolAddress((void**)&Ah,    g_Ah);
    cudaGetSymbolAddress((void**)&Bh,    g_Bh);

    cudaFuncSetAttribute(rbf_mma_kernel,
                         cudaFuncAttributeMaxDynamicSharedMemorySize, SMEM_TOTAL);

    prologue_kernel<<<(BATCH + NC) / 8, 256>>>(inputs, centers, sigmas,
                                               Ah, Bh, xsq, csq, inv2s);

    dim3 grid(NC / BN, BATCH / BM);   // (16, 64)
    rbf_mma_kernel<<<grid, 128, SMEM_TOTAL>>>(Ah, Bh, xsq, csq, inv2s, out);
}